// round 2
// baseline (speedup 1.0000x reference)
#include <cuda_runtime.h>
#include <cuda_bf16.h>
#include <math.h>

// Problem constants
#define NN 4096
#define TT 32
#define DD 158
#define NEWS 1024
#define DGRU 128
#define GG 8
#define EE 8
#define HH 4
#define KK 2
#define HID 64          // G*E
#define XDIM 1182       // D + NEWS
#define XPAD 1184       // padded to multiple of 32

// Output layout (float32, concat of tuple)
#define OFF_PRED  0
#define OFF_RW1   4096
#define OFF_HID   266240     // 4096 + 4096*64
#define OFF_TOPK  528384     // + 4096*64
#define OFF_RW2   536576     // + 4096*2

// Scratch: aggregated features [N][XPAD]  (~19.4 MB)
__device__ float g_xbuf[(size_t)NN * XPAD];

// ---------------------------------------------------------------------------
// Kernel 1: per-stock aggregation.
//   price_agg = mean over T of price_feature[n]       -> xbuf[n][0:158]
//   news_agg  = sum_t(news*m) / max(sum_t m, 1e-6)    -> xbuf[n][158:1182]
//   xbuf[n][1182:1184] = 0
// One block (256 threads) per stock. HBM-bound streaming.
// ---------------------------------------------------------------------------
__global__ void __launch_bounds__(256) agg_kernel(
    const float* __restrict__ price,   // [N,T,D]
    const float* __restrict__ news,    // [N,T,NEWS]
    const float* __restrict__ mask)    // [N,T]
{
    const int n = blockIdx.x;
    const int tid = threadIdx.x;
    __shared__ float sm[TT];
    __shared__ float sdenom;

    if (tid < TT) {
        float mv = mask[(size_t)n * TT + tid];
        sm[tid] = mv;
        float s = mv;
        #pragma unroll
        for (int o = 16; o > 0; o >>= 1) s += __shfl_xor_sync(0xffffffffu, s, o);
        if (tid == 0) sdenom = fmaxf(s, 1e-6f);
    }
    __syncthreads();
    const float inv_denom = 1.0f / sdenom;

    // news: each thread owns 4 contiguous dims (one float4)
    const float4* news4 = (const float4*)(news + (size_t)n * TT * NEWS);
    float4 acc = make_float4(0.f, 0.f, 0.f, 0.f);
    #pragma unroll 4
    for (int t = 0; t < TT; t++) {
        float4 v = news4[t * (NEWS / 4) + tid];
        float mt = sm[t];
        acc.x += mt * v.x; acc.y += mt * v.y;
        acc.z += mt * v.z; acc.w += mt * v.w;
    }
    float* xb = g_xbuf + (size_t)n * XPAD;
    xb[DD + 4 * tid + 0] = acc.x * inv_denom;
    xb[DD + 4 * tid + 1] = acc.y * inv_denom;
    xb[DD + 4 * tid + 2] = acc.z * inv_denom;
    xb[DD + 4 * tid + 3] = acc.w * inv_denom;

    // price
    if (tid < DD) {
        float a = 0.f;
        const float* p = price + (size_t)n * TT * DD + tid;
        #pragma unroll 4
        for (int t = 0; t < TT; t++) a += p[t * DD];
        xb[tid] = a * (1.0f / TT);
    }
    if (tid == DD) { xb[XDIM] = 0.f; xb[XDIM + 1] = 0.f; }
}

// ---------------------------------------------------------------------------
// Kernel 2: fused router GEMM + tanh + gate + top2/softmax + expert/attention
// 128 blocks x 256 threads, 32 stocks per block.
// ---------------------------------------------------------------------------
#define SB 32          // stocks per block
#define KC 32          // k-chunk

__global__ void __launch_bounds__(256) moe_kernel(
    const float* __restrict__ router_W,  // [1182,128]
    const float* __restrict__ router_b,  // [128]
    const float* __restrict__ gate_W,    // [128,64]
    const float* __restrict__ gate_b,    // [64]
    const float* __restrict__ expert_W,  // [8,8,64]
    const float* __restrict__ expert_b,  // [8,8]
    const float* __restrict__ wq, const float* __restrict__ wq_b,
    const float* __restrict__ wk, const float* __restrict__ wk_b,
    const float* __restrict__ wv, const float* __restrict__ wv_b,
    const float* __restrict__ wo, const float* __restrict__ wo_b,
    float* __restrict__ out)
{
    const int s0 = blockIdx.x * SB;
    const int tid = threadIdx.x;

    __shared__ float Hs[SB * DGRU];        // 16 KB, tanh(router) output
    __shared__ float SA[KC * 33 + KC * DGRU]; // GEMM staging; reused later
    float* Xs = SA;                 // [KC][33] padded
    float* Ws = SA + KC * 33;       // [KC][128]
    __shared__ int   Si1[SB], Si2[SB];
    __shared__ float Sw1[SB], Sw2[SB];

    // ---------------- Router GEMM: Hs = tanh(X @ W + b) -------------------
    const int rowg = tid >> 5;     // 0..7 -> stocks rowg*4 .. +3
    const int colg = tid & 31;     // 0..31 -> cols colg*4 .. +3
    float acc[4][4];
    #pragma unroll
    for (int i = 0; i < 4; i++)
        #pragma unroll
        for (int j = 0; j < 4; j++) acc[i][j] = 0.f;

    for (int kc = 0; kc < XPAD; kc += KC) {
        #pragma unroll
        for (int i = 0; i < 4; i++) {
            int idx = i * 256 + tid;
            int k = idx & 31, s = idx >> 5;
            Xs[k * 33 + s] = g_xbuf[(size_t)(s0 + s) * XPAD + kc + k];
        }
        #pragma unroll
        for (int i = 0; i < 4; i++) {
            int lin = i * 1024 + tid * 4;
            int k = lin >> 7, j = lin & 127;
            float4 w;
            if (kc + k < XDIM) w = *(const float4*)&router_W[(size_t)(kc + k) * DGRU + j];
            else               w = make_float4(0.f, 0.f, 0.f, 0.f);
            *(float4*)&Ws[k * DGRU + j] = w;
        }
        __syncthreads();
        #pragma unroll 8
        for (int kk = 0; kk < KC; kk++) {
            float x0 = Xs[kk * 33 + rowg * 4 + 0];
            float x1 = Xs[kk * 33 + rowg * 4 + 1];
            float x2 = Xs[kk * 33 + rowg * 4 + 2];
            float x3 = Xs[kk * 33 + rowg * 4 + 3];
            float4 w = *(float4*)&Ws[kk * DGRU + colg * 4];
            acc[0][0] += x0 * w.x; acc[0][1] += x0 * w.y; acc[0][2] += x0 * w.z; acc[0][3] += x0 * w.w;
            acc[1][0] += x1 * w.x; acc[1][1] += x1 * w.y; acc[1][2] += x1 * w.z; acc[1][3] += x1 * w.w;
            acc[2][0] += x2 * w.x; acc[2][1] += x2 * w.y; acc[2][2] += x2 * w.z; acc[2][3] += x2 * w.w;
            acc[3][0] += x3 * w.x; acc[3][1] += x3 * w.y; acc[3][2] += x3 * w.z; acc[3][3] += x3 * w.w;
        }
        __syncthreads();
    }
    #pragma unroll
    for (int i = 0; i < 4; i++) {
        #pragma unroll
        for (int j = 0; j < 4; j++) {
            int jj = colg * 4 + j;
            Hs[(rowg * 4 + i) * DGRU + jj] = tanhf(acc[i][j] + router_b[jj]);
        }
    }
    __syncthreads();

    // ---------------- Gate: hidden = Hs @ gate_W + b ----------------------
    // SA region reused: Hid = SA[0..2047], Out = SA[2048..4095]
    float* Hid = SA;
    float* Out = SA + SB * HID;
    {
        int s  = tid >> 3;        // 0..31
        int cg = tid & 7;         // 8 cols each
        float ga[8];
        #pragma unroll
        for (int c = 0; c < 8; c++) ga[c] = gate_b[cg * 8 + c];
        #pragma unroll 4
        for (int j = 0; j < DGRU; j++) {
            float hv = Hs[s * DGRU + j];
            float4 w0 = *(const float4*)&gate_W[j * HID + cg * 8];
            float4 w1 = *(const float4*)&gate_W[j * HID + cg * 8 + 4];
            ga[0] += hv * w0.x; ga[1] += hv * w0.y; ga[2] += hv * w0.z; ga[3] += hv * w0.w;
            ga[4] += hv * w1.x; ga[5] += hv * w1.y; ga[6] += hv * w1.z; ga[7] += hv * w1.w;
        }
        #pragma unroll
        for (int c = 0; c < 8; c++) Hid[s * HID + cg * 8 + c] = ga[c];
    }
    __syncthreads();

    // ---------------- Top-2 + softmax (thread per stock) ------------------
    if (tid < SB) {
        int s = tid;
        float best1 = -3.4e38f; int i1 = 0;
        for (int c = 0; c < HID; c++) {
            float v = Hid[s * HID + c];
            if (v > best1) { best1 = v; i1 = c; }
        }
        float best2 = -3.4e38f; int i2 = 0;
        for (int c = 0; c < HID; c++) {
            if (c == i1) continue;
            float v = Hid[s * HID + c];
            if (v > best2) { best2 = v; i2 = c; }
        }
        float e2 = expf(best2 - best1);
        float r = 1.0f / (1.0f + e2);
        Si1[s] = i1; Si2[s] = i2;
        Sw1[s] = r;  Sw2[s] = e2 * r;
    }

    // ---------------- Expert + attention (thread = (stock, group)) --------
    {
        int s = tid >> 3;
        int g = tid & 7;
        // expert_out[e] = hidden . expert_W[g][e] + b
        float eo[EE];
        #pragma unroll
        for (int e = 0; e < EE; e++) {
            float a = expert_b[g * EE + e];
            const float4* wr = (const float4*)&expert_W[((size_t)(g * EE + e)) * HID];
            const float4* hr = (const float4*)&Hid[s * HID];
            #pragma unroll
            for (int h4 = 0; h4 < HID / 4; h4++) {
                float4 w = wr[h4];
                float4 h = hr[h4];
                a += w.x * h.x + w.y * h.y + w.z * h.z + w.w * h.w;
            }
            eo[e] = a;
        }
        // q,k,v
        float q[EE], k[EE], v[EE];
        #pragma unroll
        for (int f = 0; f < EE; f++) {
            float aq = wq_b[g * EE + f];
            float ak = wk_b[g * EE + f];
            float av = wv_b[g * EE + f];
            #pragma unroll
            for (int e = 0; e < EE; e++) {
                aq += eo[e] * wq[(g * EE + f) * EE + e];
                ak += eo[e] * wk[(g * EE + f) * EE + e];
                av += eo[e] * wv[(g * EE + f) * EE + e];
            }
            q[f] = aq; k[f] = ak; v[f] = av;
        }
        // attention: qt[d][h] = q[h*2+d]; scores[d][e2] over h (4), /sqrt(2)
        const float isq = 0.70710678118654752f;
        float att[EE];
        #pragma unroll
        for (int d = 0; d < 2; d++) {
            float sc0 = 0.f, sc1 = 0.f;
            #pragma unroll
            for (int h = 0; h < HH; h++) {
                float qv = q[h * 2 + d];
                sc0 += qv * k[h * 2 + 0];
                sc1 += qv * k[h * 2 + 1];
            }
            sc0 *= isq; sc1 *= isq;
            float mx = fmaxf(sc0, sc1);
            float p0 = expf(sc0 - mx), p1 = expf(sc1 - mx);
            float rn = 1.0f / (p0 + p1);
            p0 *= rn; p1 *= rn;
            #pragma unroll
            for (int h = 0; h < HH; h++)
                att[h * 2 + d] = p0 * v[h * 2 + 0] + p1 * v[h * 2 + 1];
        }
        // output projection
        #pragma unroll
        for (int f = 0; f < EE; f++) {
            float a = wo_b[g * EE + f];
            #pragma unroll
            for (int e = 0; e < EE; e++)
                a += att[e] * wo[(g * EE + f) * EE + e];
            Out[s * HID + g * EE + f] = a;
        }
    }
    __syncthreads();

    // ---------------- Predictions + topk outputs --------------------------
    if (tid < SB) {
        int s = tid;
        int i1 = Si1[s], i2 = Si2[s];
        float pred = Sw1[s] * Out[s * HID + i1] + Sw2[s] * Out[s * HID + i2];
        out[OFF_PRED + s0 + s] = pred;
        out[OFF_TOPK + (size_t)(s0 + s) * 2 + 0] = (float)i1;
        out[OFF_TOPK + (size_t)(s0 + s) * 2 + 1] = (float)i2;
    }

    // ---------------- hidden + routing_weights (x2) writes ----------------
    #pragma unroll
    for (int i = 0; i < 2; i++) {
        int lin4 = i * 256 + tid;              // 0..511 float4s
        int s  = lin4 >> 4;                    // stock
        int c4 = lin4 & 15;                    // float4 within row
        int c  = c4 * 4;
        float4 hv = *(float4*)&Hid[s * HID + c];
        *(float4*)&out[OFF_HID + (size_t)(s0 + s) * HID + c] = hv;

        int i1 = Si1[s], i2 = Si2[s];
        float w1 = Sw1[s], w2 = Sw2[s];
        float4 rw;
        rw.x = (c + 0 == i1) ? w1 : (c + 0 == i2) ? w2 : 0.f;
        rw.y = (c + 1 == i1) ? w1 : (c + 1 == i2) ? w2 : 0.f;
        rw.z = (c + 2 == i1) ? w1 : (c + 2 == i2) ? w2 : 0.f;
        rw.w = (c + 3 == i1) ? w1 : (c + 3 == i2) ? w2 : 0.f;
        *(float4*)&out[OFF_RW1 + (size_t)(s0 + s) * HID + c] = rw;
        *(float4*)&out[OFF_RW2 + (size_t)(s0 + s) * HID + c] = rw;
    }
}

// ---------------------------------------------------------------------------
extern "C" void kernel_launch(void* const* d_in, const int* in_sizes, int n_in,
                              void* d_out, int out_size) {
    const float* price    = (const float*)d_in[0];
    const float* news     = (const float*)d_in[1];
    const float* mask     = (const float*)d_in[2];
    const float* router_W = (const float*)d_in[3];
    const float* router_b = (const float*)d_in[4];
    const float* gate_W   = (const float*)d_in[5];
    const float* gate_b   = (const float*)d_in[6];
    const float* expert_W = (const float*)d_in[7];
    const float* expert_b = (const float*)d_in[8];
    const float* wq   = (const float*)d_in[9];
    const float* wq_b = (const float*)d_in[10];
    const float* wk   = (const float*)d_in[11];
    const float* wk_b = (const float*)d_in[12];
    const float* wv   = (const float*)d_in[13];
    const float* wv_b = (const float*)d_in[14];
    const float* wo   = (const float*)d_in[15];
    const float* wo_b = (const float*)d_in[16];
    float* out = (float*)d_out;

    agg_kernel<<<NN, 256>>>(price, news, mask);
    moe_kernel<<<NN / SB, 256>>>(router_W, router_b, gate_W, gate_b,
                                 expert_W, expert_b,
                                 wq, wq_b, wk, wk_b, wv, wv_b, wo, wo_b,
                                 out);
}

// round 3
// speedup vs baseline: 1.1150x; 1.1150x over previous
#include <cuda_runtime.h>
#include <cuda_bf16.h>
#include <math.h>

// Problem constants
#define NN 4096
#define TT 32
#define DD 158
#define NEWS 1024
#define DGRU 128
#define GG 8
#define EE 8
#define HH 4
#define HID 64          // G*E
#define XDIM 1182       // D + NEWS
#define XPAD 1184       // padded to multiple of 32

// Output layout (float32, concat of tuple)
#define OFF_PRED  0
#define OFF_RW1   4096
#define OFF_HID   266240     // 4096 + 4096*64
#define OFF_TOPK  528384     // + 4096*64
#define OFF_RW2   536576     // + 4096*2

// Scratch buffers
__device__ float g_xbuf[(size_t)NN * XPAD];     // aggregated features [N][XPAD]
__device__ float g_Wt[(size_t)DGRU * XPAD];     // router_W transposed [col][k], zero-padded
__device__ float g_hid[(size_t)NN * DGRU];      // tanh(router) output

// packed fp32x2 FMA (even/odd-k partial sums)
__device__ __forceinline__ void fma2(unsigned long long &d,
                                     unsigned long long a,
                                     unsigned long long b) {
    asm("fma.rn.f32x2 %0, %1, %2, %0;" : "+l"(d) : "l"(a), "l"(b));
}

// ---------------------------------------------------------------------------
// Kernel 1: per-stock aggregation (HBM-bound streaming) + W transpose
// ---------------------------------------------------------------------------
__global__ void __launch_bounds__(256) agg_kernel(
    const float* __restrict__ price,   // [N,T,D]
    const float* __restrict__ news,    // [N,T,NEWS]
    const float* __restrict__ mask,    // [N,T]
    const float* __restrict__ router_W) // [1182,128]
{
    const int n = blockIdx.x;
    const int tid = threadIdx.x;
    __shared__ float sm[TT];
    __shared__ float sdenom;

    // W transpose side job (first 128 blocks) — overlapped with streaming
    if (n < DGRU) {
        for (int k = tid; k < XPAD; k += 256) {
            g_Wt[(size_t)n * XPAD + k] =
                (k < XDIM) ? router_W[(size_t)k * DGRU + n] : 0.f;
        }
    }

    if (tid < TT) {
        float mv = mask[(size_t)n * TT + tid];
        sm[tid] = mv;
        float s = mv;
        #pragma unroll
        for (int o = 16; o > 0; o >>= 1) s += __shfl_xor_sync(0xffffffffu, s, o);
        if (tid == 0) sdenom = fmaxf(s, 1e-6f);
    }
    __syncthreads();
    const float inv_denom = 1.0f / sdenom;

    // news: each thread owns 4 contiguous dims (one float4)
    const float4* news4 = (const float4*)(news + (size_t)n * TT * NEWS);
    float4 acc = make_float4(0.f, 0.f, 0.f, 0.f);
    #pragma unroll 8
    for (int t = 0; t < TT; t++) {
        float4 v = news4[t * (NEWS / 4) + tid];
        float mt = sm[t];
        acc.x += mt * v.x; acc.y += mt * v.y;
        acc.z += mt * v.z; acc.w += mt * v.w;
    }
    float* xb = g_xbuf + (size_t)n * XPAD;
    xb[DD + 4 * tid + 0] = acc.x * inv_denom;
    xb[DD + 4 * tid + 1] = acc.y * inv_denom;
    xb[DD + 4 * tid + 2] = acc.z * inv_denom;
    xb[DD + 4 * tid + 3] = acc.w * inv_denom;

    // price
    if (tid < DD) {
        float a = 0.f;
        const float* p = price + (size_t)n * TT * DD + tid;
        #pragma unroll 8
        for (int t = 0; t < TT; t++) a += p[t * DD];
        xb[tid] = a * (1.0f / TT);
    }
    if (tid == DD) { xb[XDIM] = 0.f; xb[XDIM + 1] = 0.f; }
}

// ---------------------------------------------------------------------------
// Kernel 2: router GEMM  g_hid = tanh(X @ W + b)
// grid = 256 blocks (128 stock tiles x 2 col halves), 256 threads.
// Block: 32 stocks x 64 cols, K = 1184 in chunks of 32.
// Thread: 4 stocks x 2 cols, f32x2 accumulators (even/odd-k partials).
// ---------------------------------------------------------------------------
#define SB2 32
#define CB  64
#define KC2 32
#define XSTR 36    // padded smem row stride (floats)

__global__ void __launch_bounds__(256) router_kernel(
    const float* __restrict__ router_b)
{
    const int bs = blockIdx.x >> 1;
    const int bc = blockIdx.x & 1;
    const int s0 = bs * SB2;
    const int c0 = bc * CB;
    const int tid = threadIdx.x;

    __shared__ float Xs[SB2 * XSTR];   // [stock][k]
    __shared__ float Ws[CB  * XSTR];   // [col][k]

    const int sg = tid >> 5;           // warp id = stock group (4 stocks)
    const int cg = tid & 31;           // lane = col group {cg, cg+32}

    // staging indices (thread loads 1 X float4 + 2 W float4 per chunk)
    const int sA = tid >> 3;           // 0..31
    const int kA = (tid & 7) * 4;      // 0..28
    const float* xsrc = g_xbuf + (size_t)(s0 + sA) * XPAD + kA;
    const float* wsrc0 = g_Wt + (size_t)(c0 + sA) * XPAD + kA;
    const float* wsrc1 = g_Wt + (size_t)(c0 + 32 + sA) * XPAD + kA;

    unsigned long long acc[4][2];
    #pragma unroll
    for (int i = 0; i < 4; i++) { acc[i][0] = 0ull; acc[i][1] = 0ull; }

    float4 px  = *(const float4*)(xsrc);
    float4 pw0 = *(const float4*)(wsrc0);
    float4 pw1 = *(const float4*)(wsrc1);

    for (int kc = 0; kc < XPAD; kc += KC2) {
        *(float4*)&Xs[sA * XSTR + kA]        = px;
        *(float4*)&Ws[sA * XSTR + kA]        = pw0;
        *(float4*)&Ws[(32 + sA) * XSTR + kA] = pw1;
        __syncthreads();

        int kn = kc + KC2;
        if (kn < XPAD) {
            px  = *(const float4*)(xsrc  + kn);
            pw0 = *(const float4*)(wsrc0 + kn);
            pw1 = *(const float4*)(wsrc1 + kn);
        }

        #pragma unroll
        for (int kk = 0; kk < KC2; kk += 4) {
            ulonglong2 w0 = *(ulonglong2*)&Ws[cg * XSTR + kk];
            ulonglong2 w1 = *(ulonglong2*)&Ws[(cg + 32) * XSTR + kk];
            #pragma unroll
            for (int i = 0; i < 4; i++) {
                ulonglong2 x = *(ulonglong2*)&Xs[(sg * 4 + i) * XSTR + kk];
                fma2(acc[i][0], x.x, w0.x);
                fma2(acc[i][0], x.y, w0.y);
                fma2(acc[i][1], x.x, w1.x);
                fma2(acc[i][1], x.y, w1.y);
            }
        }
        __syncthreads();
    }

    // epilogue: combine even/odd partials, bias, tanh, write
    const float b0 = router_b[c0 + cg];
    const float b1 = router_b[c0 + cg + 32];
    #pragma unroll
    for (int i = 0; i < 4; i++) {
        const int s = s0 + sg * 4 + i;
        float v0 = __uint_as_float((unsigned)acc[i][0]) +
                   __uint_as_float((unsigned)(acc[i][0] >> 32)) + b0;
        float v1 = __uint_as_float((unsigned)acc[i][1]) +
                   __uint_as_float((unsigned)(acc[i][1] >> 32)) + b1;
        g_hid[(size_t)s * DGRU + c0 + cg]      = tanhf(v0);
        g_hid[(size_t)s * DGRU + c0 + cg + 32] = tanhf(v1);
    }
}

// ---------------------------------------------------------------------------
// Kernel 3: gate + top2/softmax + expert/attention + outputs
// grid = 256 blocks, 16 stocks per block, 256 threads.
// ---------------------------------------------------------------------------
#define SB3 16
#define HSTR 132   // padded Hs row stride

__global__ void __launch_bounds__(256) tail_kernel(
    const float* __restrict__ gate_W,    // [128,64]
    const float* __restrict__ gate_b,    // [64]
    const float* __restrict__ expert_W,  // [8,8,64]
    const float* __restrict__ expert_b,  // [8,8]
    const float* __restrict__ wq, const float* __restrict__ wq_b,
    const float* __restrict__ wk, const float* __restrict__ wk_b,
    const float* __restrict__ wv, const float* __restrict__ wv_b,
    const float* __restrict__ wo, const float* __restrict__ wo_b,
    float* __restrict__ out)
{
    const int s0 = blockIdx.x * SB3;
    const int tid = threadIdx.x;

    __shared__ float Hs[SB3 * HSTR];   // tanh(router) rows, padded
    __shared__ float Hid[SB3 * HID];
    __shared__ float Out[SB3 * HID];
    __shared__ int   Si1[SB3], Si2[SB3];
    __shared__ float Sw1[SB3], Sw2[SB3];

    // load Hs: 16 x 128 floats = 512 float4, 2 per thread
    #pragma unroll
    for (int i = 0; i < 2; i++) {
        int idx = i * 256 + tid;
        int s = idx >> 5, kq = (idx & 31) * 4;
        *(float4*)&Hs[s * HSTR + kq] =
            *(const float4*)&g_hid[(size_t)(s0 + s) * DGRU + kq];
    }
    __syncthreads();

    // Gate: thread = (stock tid>>4, 4 cols)
    {
        int s  = tid >> 4;
        int cgp = tid & 15;
        float ga0 = gate_b[cgp * 4 + 0];
        float ga1 = gate_b[cgp * 4 + 1];
        float ga2 = gate_b[cgp * 4 + 2];
        float ga3 = gate_b[cgp * 4 + 3];
        #pragma unroll 8
        for (int j = 0; j < DGRU; j++) {
            float hv = Hs[s * HSTR + j];
            float4 w = __ldg((const float4*)&gate_W[j * HID + cgp * 4]);
            ga0 += hv * w.x; ga1 += hv * w.y; ga2 += hv * w.z; ga3 += hv * w.w;
        }
        Hid[s * HID + cgp * 4 + 0] = ga0;
        Hid[s * HID + cgp * 4 + 1] = ga1;
        Hid[s * HID + cgp * 4 + 2] = ga2;
        Hid[s * HID + cgp * 4 + 3] = ga3;
    }
    __syncthreads();

    // Top-2 + softmax, thread per stock
    if (tid < SB3) {
        int s = tid;
        float best1 = -3.4e38f; int i1 = 0;
        for (int c = 0; c < HID; c++) {
            float v = Hid[s * HID + c];
            if (v > best1) { best1 = v; i1 = c; }
        }
        float best2 = -3.4e38f; int i2 = 0;
        for (int c = 0; c < HID; c++) {
            if (c == i1) continue;
            float v = Hid[s * HID + c];
            if (v > best2) { best2 = v; i2 = c; }
        }
        float e2 = expf(best2 - best1);
        float r = 1.0f / (1.0f + e2);
        Si1[s] = i1; Si2[s] = i2;
        Sw1[s] = r;  Sw2[s] = e2 * r;
    }

    // Expert + attention: thread = (stock, group), 128 active threads
    if (tid < SB3 * GG) {
        int s = tid >> 3;
        int g = tid & 7;
        float eo[EE];
        #pragma unroll
        for (int e = 0; e < EE; e++) {
            float a = expert_b[g * EE + e];
            const float4* wr = (const float4*)&expert_W[((size_t)(g * EE + e)) * HID];
            const float4* hr = (const float4*)&Hid[s * HID];
            #pragma unroll
            for (int h4 = 0; h4 < HID / 4; h4++) {
                float4 w = wr[h4];
                float4 h = hr[h4];
                a += w.x * h.x + w.y * h.y + w.z * h.z + w.w * h.w;
            }
            eo[e] = a;
        }
        float q[EE], k[EE], v[EE];
        #pragma unroll
        for (int f = 0; f < EE; f++) {
            float aq = wq_b[g * EE + f];
            float ak = wk_b[g * EE + f];
            float av = wv_b[g * EE + f];
            #pragma unroll
            for (int e = 0; e < EE; e++) {
                aq += eo[e] * wq[(g * EE + f) * EE + e];
                ak += eo[e] * wk[(g * EE + f) * EE + e];
                av += eo[e] * wv[(g * EE + f) * EE + e];
            }
            q[f] = aq; k[f] = ak; v[f] = av;
        }
        const float isq = 0.70710678118654752f;
        float att[EE];
        #pragma unroll
        for (int d = 0; d < 2; d++) {
            float sc0 = 0.f, sc1 = 0.f;
            #pragma unroll
            for (int h = 0; h < HH; h++) {
                float qv = q[h * 2 + d];
                sc0 += qv * k[h * 2 + 0];
                sc1 += qv * k[h * 2 + 1];
            }
            sc0 *= isq; sc1 *= isq;
            float mx = fmaxf(sc0, sc1);
            float p0 = expf(sc0 - mx), p1 = expf(sc1 - mx);
            float rn = 1.0f / (p0 + p1);
            p0 *= rn; p1 *= rn;
            #pragma unroll
            for (int h = 0; h < HH; h++)
                att[h * 2 + d] = p0 * v[h * 2 + 0] + p1 * v[h * 2 + 1];
        }
        #pragma unroll
        for (int f = 0; f < EE; f++) {
            float a = wo_b[g * EE + f];
            #pragma unroll
            for (int e = 0; e < EE; e++)
                a += att[e] * wo[(g * EE + f) * EE + e];
            Out[s * HID + g * EE + f] = a;
        }
    }
    __syncthreads();

    // predictions + topk
    if (tid < SB3) {
        int s = tid;
        int i1 = Si1[s], i2 = Si2[s];
        float pred = Sw1[s] * Out[s * HID + i1] + Sw2[s] * Out[s * HID + i2];
        out[OFF_PRED + s0 + s] = pred;
        out[OFF_TOPK + (size_t)(s0 + s) * 2 + 0] = (float)i1;
        out[OFF_TOPK + (size_t)(s0 + s) * 2 + 1] = (float)i2;
    }

    // hidden + routing_weights (x2): 16 stocks x 64 cols = 256 float4
    if (tid < 256) {
        int s  = tid >> 4;
        int c  = (tid & 15) * 4;
        float4 hv = *(float4*)&Hid[s * HID + c];
        *(float4*)&out[OFF_HID + (size_t)(s0 + s) * HID + c] = hv;

        int i1 = Si1[s], i2 = Si2[s];
        float w1 = Sw1[s], w2 = Sw2[s];
        float4 rw;
        rw.x = (c + 0 == i1) ? w1 : (c + 0 == i2) ? w2 : 0.f;
        rw.y = (c + 1 == i1) ? w1 : (c + 1 == i2) ? w2 : 0.f;
        rw.z = (c + 2 == i1) ? w1 : (c + 2 == i2) ? w2 : 0.f;
        rw.w = (c + 3 == i1) ? w1 : (c + 3 == i2) ? w2 : 0.f;
        *(float4*)&out[OFF_RW1 + (size_t)(s0 + s) * HID + c] = rw;
        *(float4*)&out[OFF_RW2 + (size_t)(s0 + s) * HID + c] = rw;
    }
}

// ---------------------------------------------------------------------------
extern "C" void kernel_launch(void* const* d_in, const int* in_sizes, int n_in,
                              void* d_out, int out_size) {
    const float* price    = (const float*)d_in[0];
    const float* news     = (const float*)d_in[1];
    const float* mask     = (const float*)d_in[2];
    const float* router_W = (const float*)d_in[3];
    const float* router_b = (const float*)d_in[4];
    const float* gate_W   = (const float*)d_in[5];
    const float* gate_b   = (const float*)d_in[6];
    const float* expert_W = (const float*)d_in[7];
    const float* expert_b = (const float*)d_in[8];
    const float* wq   = (const float*)d_in[9];
    const float* wq_b = (const float*)d_in[10];
    const float* wk   = (const float*)d_in[11];
    const float* wk_b = (const float*)d_in[12];
    const float* wv   = (const float*)d_in[13];
    const float* wv_b = (const float*)d_in[14];
    const float* wo   = (const float*)d_in[15];
    const float* wo_b = (const float*)d_in[16];
    float* out = (float*)d_out;

    agg_kernel<<<NN, 256>>>(price, news, mask, router_W);
    router_kernel<<<(NN / SB2) * 2, 256>>>(router_b);
    tail_kernel<<<NN / SB3, 256>>>(gate_W, gate_b, expert_W, expert_b,
                                   wq, wq_b, wk, wk_b, wv, wv_b, wo, wo_b,
                                   out);
}